// round 5
// baseline (speedup 1.0000x reference)
#include <cuda_runtime.h>
#include <math.h>
#include <stdint.h>

#define BB 2
#define SQ 2048
#define SKV 4096
#define DM 1024
#define NH 16
#define DK 64

// ---------------- scratch (device globals; no allocation allowed) ----------------
__device__ float g_normed[(size_t)BB * SQ * DM];
__device__ float g_q[(size_t)BB * SQ * DM];
__device__ float g_k[(size_t)BB * SKV * DM];
__device__ float g_v[(size_t)BB * SKV * DM];
__device__ float g_ctx[(size_t)BB * SQ * DM];

// ---------------- helpers ----------------
__device__ __forceinline__ uint32_t f2tf32(float x) {
    uint32_t u;
    asm("cvt.rna.tf32.f32 %0, %1;" : "=r"(u) : "f"(x));
    return u;
}

__device__ __forceinline__ void mma_tf32(float* c, const uint32_t* a, const uint32_t* b) {
    asm volatile(
        "mma.sync.aligned.m16n8k8.row.col.f32.tf32.tf32.f32 "
        "{%0,%1,%2,%3}, {%4,%5,%6,%7}, {%8,%9}, {%0,%1,%2,%3};"
        : "+f"(c[0]), "+f"(c[1]), "+f"(c[2]), "+f"(c[3])
        : "r"(a[0]), "r"(a[1]), "r"(a[2]), "r"(a[3]), "r"(b[0]), "r"(b[1]));
}

// FMA-pipe exp (no MUFU). exp(x) = 2^(x*log2e); n by magic-number rounding,
// 2^f degree-5 poly on [-0.5, 0.5], exponent spliced via integer add.
__device__ __forceinline__ float fast_exp(float x) {
    x = fmaxf(x, -87.0f);                         // keep n in range (handles -1e30 init)
    float y = fmaf(x, 1.442695041f, 12582912.0f); // 1.5*2^23 magic: rn to int in mantissa
    int n = __float_as_int(y) - 0x4B400000;       // n = round(x*log2e)
    float f = fmaf(x, 1.442695041f, -(y - 12582912.0f)); // f in [-0.5, 0.5]
    float p = 1.333355815e-3f;
    p = fmaf(p, f, 9.618129107e-3f);
    p = fmaf(p, f, 5.550410866e-2f);
    p = fmaf(p, f, 2.402265069e-1f);
    p = fmaf(p, f, 6.931471806e-1f);
    p = fmaf(p, f, 1.0f);                         // p = 2^f in [~0.707, ~1.414]
    return __int_as_float(__float_as_int(p) + (n << 23));
}

// ---------------- RMSNorm ----------------
__global__ void rmsnorm_kernel(const float* __restrict__ x, const float* __restrict__ w) {
    int row = blockIdx.x;
    const float* xr = x + (size_t)row * DM;
    int i = threadIdx.x * 4;
    float4 xv = *(const float4*)(xr + i);
    float s = xv.x * xv.x + xv.y * xv.y + xv.z * xv.z + xv.w * xv.w;
#pragma unroll
    for (int off = 16; off > 0; off >>= 1) s += __shfl_xor_sync(0xffffffffu, s, off);
    __shared__ float red[8];
    int wid = threadIdx.x >> 5, lane = threadIdx.x & 31;
    if (lane == 0) red[wid] = s;
    __syncthreads();
    float tot = 0.f;
#pragma unroll
    for (int k = 0; k < 8; k++) tot += red[k];
    float inv = rsqrtf(tot * (1.0f / DM) + 1e-6f);
    float4 wv = *(const float4*)(w + i);
    *(float4*)&g_normed[(size_t)row * DM + i] =
        make_float4(wv.x * xv.x * inv, wv.y * xv.y * inv, wv.z * xv.z * inv, wv.w * xv.w * inv);
}

// ---------------- tf32 GEMM (R3 config: 128 thr, 4 warps of 64x64, tile 128x128x16) ----------------
#define GBK 16
#define LDA 140
#define LDB 136

template <bool RES>
__global__ __launch_bounds__(128) void tf32_gemm(const float* __restrict__ A,
                                                 const float* __restrict__ B,
                                                 const float* __restrict__ Res,
                                                 float* __restrict__ C,
                                                 int M, int N, int K) {
    __shared__ uint32_t As[2][GBK][LDA];
    __shared__ uint32_t Bs[2][GBK][LDB];
    int tid = threadIdx.x;
    int wid = tid >> 5, lane = tid & 31;
    int g = lane >> 2, tig = lane & 3;
    int warp_m = (wid >> 1) * 64, warp_n = (wid & 1) * 64;
    int m0 = blockIdx.y * 128, n0 = blockIdx.x * 128;

    float acc[4][8][4];
#pragma unroll
    for (int mt = 0; mt < 4; mt++)
#pragma unroll
        for (int nt = 0; nt < 8; nt++)
#pragma unroll
            for (int e = 0; e < 4; e++) acc[mt][nt][e] = 0.f;

    const float* ap = A + (size_t)(m0 + tid) * K;
    float4 pa[4], pb[4];

#pragma unroll
    for (int i = 0; i < 4; i++) pa[i] = *(const float4*)(ap + i * 4);
#pragma unroll
    for (int i = 0; i < 4; i++) {
        int idx = tid + 128 * i;
        int r = idx >> 5, c4 = (idx & 31) * 4;
        pb[i] = *(const float4*)(B + (size_t)r * N + n0 + c4);
    }
#pragma unroll
    for (int i = 0; i < 4; i++) {
        As[0][i * 4 + 0][tid] = f2tf32(pa[i].x);
        As[0][i * 4 + 1][tid] = f2tf32(pa[i].y);
        As[0][i * 4 + 2][tid] = f2tf32(pa[i].z);
        As[0][i * 4 + 3][tid] = f2tf32(pa[i].w);
    }
#pragma unroll
    for (int i = 0; i < 4; i++) {
        int idx = tid + 128 * i;
        int r = idx >> 5, c4 = (idx & 31) * 4;
        *(uint4*)&Bs[0][r][c4] =
            make_uint4(f2tf32(pb[i].x), f2tf32(pb[i].y), f2tf32(pb[i].z), f2tf32(pb[i].w));
    }
    __syncthreads();

    int nt_tiles = K / GBK;
    for (int kt = 0; kt < nt_tiles; kt++) {
        int buf = kt & 1;
        if (kt + 1 < nt_tiles) {
            int k0 = (kt + 1) * GBK;
#pragma unroll
            for (int i = 0; i < 4; i++) pa[i] = *(const float4*)(ap + k0 + i * 4);
#pragma unroll
            for (int i = 0; i < 4; i++) {
                int idx = tid + 128 * i;
                int r = idx >> 5, c4 = (idx & 31) * 4;
                pb[i] = *(const float4*)(B + (size_t)(k0 + r) * N + n0 + c4);
            }
        }
#pragma unroll
        for (int ks = 0; ks < 2; ks++) {
            int kb = ks * 8;
            uint32_t af[4][4], bf[8][2];
#pragma unroll
            for (int mt = 0; mt < 4; mt++) {
                int mm = warp_m + mt * 16 + g;
                af[mt][0] = As[buf][kb + tig][mm];
                af[mt][1] = As[buf][kb + tig][mm + 8];
                af[mt][2] = As[buf][kb + tig + 4][mm];
                af[mt][3] = As[buf][kb + tig + 4][mm + 8];
            }
#pragma unroll
            for (int ntl = 0; ntl < 8; ntl++) {
                int nn = warp_n + ntl * 8 + g;
                bf[ntl][0] = Bs[buf][kb + tig][nn];
                bf[ntl][1] = Bs[buf][kb + tig + 4][nn];
            }
#pragma unroll
            for (int mt = 0; mt < 4; mt++)
#pragma unroll
                for (int ntl = 0; ntl < 8; ntl++) mma_tf32(acc[mt][ntl], af[mt], bf[ntl]);
        }
        if (kt + 1 < nt_tiles) {
            int nb = buf ^ 1;
#pragma unroll
            for (int i = 0; i < 4; i++) {
                As[nb][i * 4 + 0][tid] = f2tf32(pa[i].x);
                As[nb][i * 4 + 1][tid] = f2tf32(pa[i].y);
                As[nb][i * 4 + 2][tid] = f2tf32(pa[i].z);
                As[nb][i * 4 + 3][tid] = f2tf32(pa[i].w);
            }
#pragma unroll
            for (int i = 0; i < 4; i++) {
                int idx = tid + 128 * i;
                int r = idx >> 5, c4 = (idx & 31) * 4;
                *(uint4*)&Bs[nb][r][c4] =
                    make_uint4(f2tf32(pb[i].x), f2tf32(pb[i].y), f2tf32(pb[i].z), f2tf32(pb[i].w));
            }
            __syncthreads();
        }
    }

#pragma unroll
    for (int mt = 0; mt < 4; mt++) {
#pragma unroll
        for (int ntl = 0; ntl < 8; ntl++) {
            int row = m0 + warp_m + mt * 16 + g;
            int col = n0 + warp_n + ntl * 8 + 2 * tig;
            size_t i0 = (size_t)row * N + col;
            size_t i1 = (size_t)(row + 8) * N + col;
            float2 v0 = make_float2(acc[mt][ntl][0], acc[mt][ntl][1]);
            float2 v1 = make_float2(acc[mt][ntl][2], acc[mt][ntl][3]);
            if (RES) {
                float2 r0 = *(const float2*)&Res[i0];
                float2 r1 = *(const float2*)&Res[i1];
                v0.x += r0.x; v0.y += r0.y;
                v1.x += r1.x; v1.y += r1.y;
            }
            *(float2*)&C[i0] = v0;
            *(float2*)&C[i1] = v1;
        }
    }
}

// ---------------- Flash attention: tf32 mma, register P, FMA-pipe exp ----------------
#define ALDQ 140
#define ALDK 72
#define ATTN_SMEM_U32 (64 * ALDQ + 2 * 64 * ALDK)

__global__ __launch_bounds__(256, 1) void attn_tf32(const float* __restrict__ mask) {
    extern __shared__ uint32_t sm[];
    uint32_t* Qs = sm;              // [64][ALDQ]  (d, q)
    uint32_t* Ks = Qs + 64 * ALDQ;  // [64][ALDK]  (d, kv)
    uint32_t* Vs = Ks + 64 * ALDK;  // [64][ALDK]  (kv-permuted, d)

    int b = blockIdx.z, h = blockIdx.y;
    int q0 = blockIdx.x * 128;
    int tid = threadIdx.x;
    int wid = tid >> 5, lane = tid & 31;
    int g = lane >> 2, tig = lane & 3;
    int mbase = wid * 16;

    const float* mrow = mask + (size_t)b * SKV;

    // stage Q transposed: Qs[d][q]
    {
        int qrow = tid & 127, half = tid >> 7;
        const float* qp = g_q + (size_t)(b * SQ + q0 + qrow) * DM + h * DK + half * 32;
#pragma unroll
        for (int i = 0; i < 8; i++) {
            float4 v = *(const float4*)(qp + i * 4);
            int d0 = half * 32 + i * 4;
            Qs[(d0 + 0) * ALDQ + qrow] = f2tf32(v.x);
            Qs[(d0 + 1) * ALDQ + qrow] = f2tf32(v.y);
            Qs[(d0 + 2) * ALDQ + qrow] = f2tf32(v.z);
            Qs[(d0 + 3) * ALDQ + qrow] = f2tf32(v.w);
        }
    }
    __syncthreads();

    // hoist Q fragments (loop-invariant)
    uint32_t qreg[8][4];
#pragma unroll
    for (int ks = 0; ks < 8; ks++) {
        int kb = ks * 8;
        qreg[ks][0] = Qs[(kb + tig) * ALDQ + mbase + g];
        qreg[ks][1] = Qs[(kb + tig) * ALDQ + mbase + g + 8];
        qreg[ks][2] = Qs[(kb + tig + 4) * ALDQ + mbase + g];
        qreg[ks][3] = Qs[(kb + tig + 4) * ALDQ + mbase + g + 8];
    }

    float m0s = -1e30f, m1s = -1e30f, l0 = 0.f, l1 = 0.f;
    float oacc[8][4];
#pragma unroll
    for (int d = 0; d < 8; d++)
#pragma unroll
        for (int e = 0; e < 4; e++) oacc[d][e] = 0.f;

    for (int jt = 0; jt < SKV / 64; jt++) {
        __syncthreads();
        // stage K transposed, V with permuted rows (pos = (j>>1)+(j&1)*4 within 8-group)
        {
            int r = tid & 63, ch = tid >> 6;
            const float* kp = g_k + (size_t)(b * SKV + jt * 64 + r) * DM + h * DK + ch * 16;
            const float* vp = g_v + (size_t)(b * SKV + jt * 64 + r) * DM + h * DK + ch * 16;
            int j = r & 7;
            int prow = (r & ~7) | ((j >> 1) + (j & 1) * 4);
#pragma unroll
            for (int i = 0; i < 4; i++) {
                float4 v = *(const float4*)(kp + i * 4);
                int d0 = ch * 16 + i * 4;
                Ks[(d0 + 0) * ALDK + r] = f2tf32(v.x);
                Ks[(d0 + 1) * ALDK + r] = f2tf32(v.y);
                Ks[(d0 + 2) * ALDK + r] = f2tf32(v.z);
                Ks[(d0 + 3) * ALDK + r] = f2tf32(v.w);
            }
#pragma unroll
            for (int i = 0; i < 4; i++) {
                float4 v = *(const float4*)(vp + i * 4);
                int d0 = ch * 16 + i * 4;
                *(uint4*)&Vs[prow * ALDK + d0] =
                    make_uint4(f2tf32(v.x), f2tf32(v.y), f2tf32(v.z), f2tf32(v.w));
            }
        }
        __syncthreads();

        // S = Q @ K^T
        float sacc[8][4];
#pragma unroll
        for (int n = 0; n < 8; n++)
#pragma unroll
            for (int e = 0; e < 4; e++) sacc[n][e] = 0.f;
#pragma unroll
        for (int ks = 0; ks < 8; ks++) {
            int kb = ks * 8;
#pragma unroll
            for (int n = 0; n < 8; n++) {
                uint32_t bf[2];
                bf[0] = Ks[(kb + tig) * ALDK + n * 8 + g];
                bf[1] = Ks[(kb + tig + 4) * ALDK + n * 8 + g];
                mma_tf32(sacc[n], qreg[ks], bf);
            }
        }

        // mask + online softmax (registers, FMA-pipe exp)
        float rmax0 = -1e30f, rmax1 = -1e30f;
#pragma unroll
        for (int n = 0; n < 8; n++) {
            float2 mk = *(const float2*)&mrow[jt * 64 + n * 8 + 2 * tig];
            sacc[n][0] += mk.x; sacc[n][1] += mk.y;
            sacc[n][2] += mk.x; sacc[n][3] += mk.y;
            rmax0 = fmaxf(rmax0, fmaxf(sacc[n][0], sacc[n][1]));
            rmax1 = fmaxf(rmax1, fmaxf(sacc[n][2], sacc[n][3]));
        }
        rmax0 = fmaxf(rmax0, __shfl_xor_sync(0xffffffffu, rmax0, 1));
        rmax0 = fmaxf(rmax0, __shfl_xor_sync(0xffffffffu, rmax0, 2));
        rmax1 = fmaxf(rmax1, __shfl_xor_sync(0xffffffffu, rmax1, 1));
        rmax1 = fmaxf(rmax1, __shfl_xor_sync(0xffffffffu, rmax1, 2));
        float mn0 = fmaxf(m0s, rmax0), mn1 = fmaxf(m1s, rmax1);
        float sc0 = fast_exp(m0s - mn0), sc1 = fast_exp(m1s - mn1);
        m0s = mn0; m1s = mn1;
#pragma unroll
        for (int d = 0; d < 8; d++) {
            oacc[d][0] *= sc0; oacc[d][1] *= sc0;
            oacc[d][2] *= sc1; oacc[d][3] *= sc1;
        }
        float rs0 = 0.f, rs1 = 0.f;
#pragma unroll
        for (int n = 0; n < 8; n++) {
            sacc[n][0] = fast_exp(sacc[n][0] - mn0);
            sacc[n][1] = fast_exp(sacc[n][1] - mn0);
            sacc[n][2] = fast_exp(sacc[n][2] - mn1);
            sacc[n][3] = fast_exp(sacc[n][3] - mn1);
            rs0 += sacc[n][0] + sacc[n][1];
            rs1 += sacc[n][2] + sacc[n][3];
        }
        rs0 += __shfl_xor_sync(0xffffffffu, rs0, 1);
        rs0 += __shfl_xor_sync(0xffffffffu, rs0, 2);
        rs1 += __shfl_xor_sync(0xffffffffu, rs1, 1);
        rs1 += __shfl_xor_sync(0xffffffffu, rs1, 2);
        l0 = l0 * sc0 + rs0;
        l1 = l1 * sc1 + rs1;

        // O += P @ V (P a-frag from registers; V rows permuted to match C-frag layout)
#pragma unroll
        for (int ks = 0; ks < 8; ks++) {
            int kb = ks * 8;
            uint32_t pf[4];
            pf[0] = f2tf32(sacc[ks][0]);
            pf[1] = f2tf32(sacc[ks][2]);
            pf[2] = f2tf32(sacc[ks][1]);
            pf[3] = f2tf32(sacc[ks][3]);
#pragma unroll
            for (int n = 0; n < 8; n++) {
                uint32_t vf[2];
                vf[0] = Vs[(kb + tig) * ALDK + n * 8 + g];
                vf[1] = Vs[(kb + tig + 4) * ALDK + n * 8 + g];
                mma_tf32(oacc[n], pf, vf);
            }
        }
    }

    float inv0 = 1.0f / l0, inv1 = 1.0f / l1;
    int row0 = q0 + mbase + g;
    float* cp0 = g_ctx + (size_t)(b * SQ + row0) * DM + h * DK;
    float* cp1 = g_ctx + (size_t)(b * SQ + row0 + 8) * DM + h * DK;
#pragma unroll
    for (int n = 0; n < 8; n++) {
        int col = n * 8 + 2 * tig;
        *(float2*)&cp0[col] = make_float2(oacc[n][0] * inv0, oacc[n][1] * inv0);
        *(float2*)&cp1[col] = make_float2(oacc[n][2] * inv1, oacc[n][3] * inv1);
    }
}

// ---------------- launch ----------------
extern "C" void kernel_launch(void* const* d_in, const int* in_sizes, int n_in,
                              void* d_out, int out_size) {
    const float* hidden = (const float*)d_in[0];
    const float* kv     = (const float*)d_in[1];
    const float* mask   = (const float*)d_in[2];
    const float* lnw    = (const float*)d_in[3];
    const float* Wq     = (const float*)d_in[4];
    const float* Wk     = (const float*)d_in[5];
    const float* Wv     = (const float*)d_in[6];
    const float* Wo     = (const float*)d_in[7];
    float* out = (float*)d_out;

    float *p_normed, *p_q, *p_k, *p_v, *p_ctx;
    cudaGetSymbolAddress((void**)&p_normed, g_normed);
    cudaGetSymbolAddress((void**)&p_q, g_q);
    cudaGetSymbolAddress((void**)&p_k, g_k);
    cudaGetSymbolAddress((void**)&p_v, g_v);
    cudaGetSymbolAddress((void**)&p_ctx, g_ctx);

    rmsnorm_kernel<<<BB * SQ, 256>>>(hidden, lnw);

    dim3 gq(DM / 128, (BB * SQ) / 128);
    dim3 gkv(DM / 128, (BB * SKV) / 128);
    tf32_gemm<false><<<gq, 128>>>(p_normed, Wq, nullptr, p_q, BB * SQ, DM, DM);
    tf32_gemm<false><<<gkv, 128>>>(kv, Wk, nullptr, p_k, BB * SKV, DM, DM);
    tf32_gemm<false><<<gkv, 128>>>(kv, Wv, nullptr, p_v, BB * SKV, DM, DM);

    const int ATTN_SMEM = ATTN_SMEM_U32 * 4;
    cudaFuncSetAttribute(attn_tf32, cudaFuncAttributeMaxDynamicSharedMemorySize, ATTN_SMEM);
    dim3 ga(SQ / 128, NH, BB);
    attn_tf32<<<ga, 256, ATTN_SMEM>>>(mask);

    tf32_gemm<true><<<gq, 128>>>(p_ctx, Wo, hidden, out, BB * SQ, DM, DM);
}

// round 6
// speedup vs baseline: 1.8106x; 1.8106x over previous
#include <cuda_runtime.h>
#include <math.h>
#include <stdint.h>

#define BB 2
#define SQ 2048
#define SKV 4096
#define DM 1024
#define NH 16
#define DK 64

// ---------------- scratch (device globals; no allocation allowed) ----------------
__device__ float g_normed[(size_t)BB * SQ * DM];
__device__ float g_q[(size_t)BB * SQ * DM];
__device__ float g_k[(size_t)BB * SKV * DM];
__device__ float g_v[(size_t)BB * SKV * DM];
__device__ float g_ctx[(size_t)BB * SQ * DM];

// ---------------- helpers ----------------
__device__ __forceinline__ uint32_t f2tf32(float x) {
    uint32_t u;
    asm("cvt.rna.tf32.f32 %0, %1;" : "=r"(u) : "f"(x));
    return u;
}

__device__ __forceinline__ void mma_tf32(float* c, const uint32_t* a, const uint32_t* b) {
    asm volatile(
        "mma.sync.aligned.m16n8k8.row.col.f32.tf32.tf32.f32 "
        "{%0,%1,%2,%3}, {%4,%5,%6,%7}, {%8,%9}, {%0,%1,%2,%3};"
        : "+f"(c[0]), "+f"(c[1]), "+f"(c[2]), "+f"(c[3])
        : "r"(a[0]), "r"(a[1]), "r"(a[2]), "r"(a[3]), "r"(b[0]), "r"(b[1]));
}

// FMA-pipe exp (no MUFU)
__device__ __forceinline__ float fast_exp(float x) {
    x = fmaxf(x, -87.0f);
    float y = fmaf(x, 1.442695041f, 12582912.0f);
    int n = __float_as_int(y) - 0x4B400000;
    float f = fmaf(x, 1.442695041f, -(y - 12582912.0f));
    float p = 1.333355815e-3f;
    p = fmaf(p, f, 9.618129107e-3f);
    p = fmaf(p, f, 5.550410866e-2f);
    p = fmaf(p, f, 2.402265069e-1f);
    p = fmaf(p, f, 6.931471806e-1f);
    p = fmaf(p, f, 1.0f);
    return __int_as_float(__float_as_int(p) + (n << 23));
}

#define CP_ASYNC16(dst_u32, src_ptr) \
    asm volatile("cp.async.ca.shared.global [%0], [%1], 16;\n" :: "r"(dst_u32), "l"(src_ptr))
#define CP_COMMIT() asm volatile("cp.async.commit_group;\n" ::: "memory")

// ---------------- RMSNorm ----------------
__global__ void rmsnorm_kernel(const float* __restrict__ x, const float* __restrict__ w) {
    int row = blockIdx.x;
    const float* xr = x + (size_t)row * DM;
    int i = threadIdx.x * 4;
    float4 xv = *(const float4*)(xr + i);
    float s = xv.x * xv.x + xv.y * xv.y + xv.z * xv.z + xv.w * xv.w;
#pragma unroll
    for (int off = 16; off > 0; off >>= 1) s += __shfl_xor_sync(0xffffffffu, s, off);
    __shared__ float red[8];
    int wid = threadIdx.x >> 5, lane = threadIdx.x & 31;
    if (lane == 0) red[wid] = s;
    __syncthreads();
    float tot = 0.f;
#pragma unroll
    for (int k = 0; k < 8; k++) tot += red[k];
    float inv = rsqrtf(tot * (1.0f / DM) + 1e-6f);
    float4 wv = *(const float4*)(w + i);
    *(float4*)&g_normed[(size_t)row * DM + i] =
        make_float4(wv.x * xv.x * inv, wv.y * xv.y * inv, wv.z * xv.z * inv, wv.w * xv.w * inv);
}

// ---------------- tf32 GEMM (R3 config). CVT: round outputs to tf32 for attention. ----------------
#define GBK 16
#define LDA 140
#define LDB 136

template <bool RES, bool CVT>
__global__ __launch_bounds__(128) void tf32_gemm(const float* __restrict__ A,
                                                 const float* __restrict__ B,
                                                 const float* __restrict__ Res,
                                                 float* __restrict__ C,
                                                 int M, int N, int K) {
    __shared__ uint32_t As[2][GBK][LDA];
    __shared__ uint32_t Bs[2][GBK][LDB];
    int tid = threadIdx.x;
    int wid = tid >> 5, lane = tid & 31;
    int g = lane >> 2, tig = lane & 3;
    int warp_m = (wid >> 1) * 64, warp_n = (wid & 1) * 64;
    int m0 = blockIdx.y * 128, n0 = blockIdx.x * 128;

    float acc[4][8][4];
#pragma unroll
    for (int mt = 0; mt < 4; mt++)
#pragma unroll
        for (int nt = 0; nt < 8; nt++)
#pragma unroll
            for (int e = 0; e < 4; e++) acc[mt][nt][e] = 0.f;

    const float* ap = A + (size_t)(m0 + tid) * K;
    float4 pa[4], pb[4];

#pragma unroll
    for (int i = 0; i < 4; i++) pa[i] = *(const float4*)(ap + i * 4);
#pragma unroll
    for (int i = 0; i < 4; i++) {
        int idx = tid + 128 * i;
        int r = idx >> 5, c4 = (idx & 31) * 4;
        pb[i] = *(const float4*)(B + (size_t)r * N + n0 + c4);
    }
#pragma unroll
    for (int i = 0; i < 4; i++) {
        As[0][i * 4 + 0][tid] = f2tf32(pa[i].x);
        As[0][i * 4 + 1][tid] = f2tf32(pa[i].y);
        As[0][i * 4 + 2][tid] = f2tf32(pa[i].z);
        As[0][i * 4 + 3][tid] = f2tf32(pa[i].w);
    }
#pragma unroll
    for (int i = 0; i < 4; i++) {
        int idx = tid + 128 * i;
        int r = idx >> 5, c4 = (idx & 31) * 4;
        *(uint4*)&Bs[0][r][c4] =
            make_uint4(f2tf32(pb[i].x), f2tf32(pb[i].y), f2tf32(pb[i].z), f2tf32(pb[i].w));
    }
    __syncthreads();

    int nt_tiles = K / GBK;
    for (int kt = 0; kt < nt_tiles; kt++) {
        int buf = kt & 1;
        if (kt + 1 < nt_tiles) {
            int k0 = (kt + 1) * GBK;
#pragma unroll
            for (int i = 0; i < 4; i++) pa[i] = *(const float4*)(ap + k0 + i * 4);
#pragma unroll
            for (int i = 0; i < 4; i++) {
                int idx = tid + 128 * i;
                int r = idx >> 5, c4 = (idx & 31) * 4;
                pb[i] = *(const float4*)(B + (size_t)(k0 + r) * N + n0 + c4);
            }
        }
#pragma unroll
        for (int ks = 0; ks < 2; ks++) {
            int kb = ks * 8;
            uint32_t af[4][4], bf[8][2];
#pragma unroll
            for (int mt = 0; mt < 4; mt++) {
                int mm = warp_m + mt * 16 + g;
                af[mt][0] = As[buf][kb + tig][mm];
                af[mt][1] = As[buf][kb + tig][mm + 8];
                af[mt][2] = As[buf][kb + tig + 4][mm];
                af[mt][3] = As[buf][kb + tig + 4][mm + 8];
            }
#pragma unroll
            for (int ntl = 0; ntl < 8; ntl++) {
                int nn = warp_n + ntl * 8 + g;
                bf[ntl][0] = Bs[buf][kb + tig][nn];
                bf[ntl][1] = Bs[buf][kb + tig + 4][nn];
            }
#pragma unroll
            for (int mt = 0; mt < 4; mt++)
#pragma unroll
                for (int ntl = 0; ntl < 8; ntl++) mma_tf32(acc[mt][ntl], af[mt], bf[ntl]);
        }
        if (kt + 1 < nt_tiles) {
            int nb = buf ^ 1;
#pragma unroll
            for (int i = 0; i < 4; i++) {
                As[nb][i * 4 + 0][tid] = f2tf32(pa[i].x);
                As[nb][i * 4 + 1][tid] = f2tf32(pa[i].y);
                As[nb][i * 4 + 2][tid] = f2tf32(pa[i].z);
                As[nb][i * 4 + 3][tid] = f2tf32(pa[i].w);
            }
#pragma unroll
            for (int i = 0; i < 4; i++) {
                int idx = tid + 128 * i;
                int r = idx >> 5, c4 = (idx & 31) * 4;
                *(uint4*)&Bs[nb][r][c4] =
                    make_uint4(f2tf32(pb[i].x), f2tf32(pb[i].y), f2tf32(pb[i].z), f2tf32(pb[i].w));
            }
            __syncthreads();
        }
    }

#pragma unroll
    for (int mt = 0; mt < 4; mt++) {
#pragma unroll
        for (int ntl = 0; ntl < 8; ntl++) {
            int row = m0 + warp_m + mt * 16 + g;
            int col = n0 + warp_n + ntl * 8 + 2 * tig;
            size_t i0 = (size_t)row * N + col;
            size_t i1 = (size_t)(row + 8) * N + col;
            float2 v0 = make_float2(acc[mt][ntl][0], acc[mt][ntl][1]);
            float2 v1 = make_float2(acc[mt][ntl][2], acc[mt][ntl][3]);
            if (RES) {
                float2 r0 = *(const float2*)&Res[i0];
                float2 r1 = *(const float2*)&Res[i1];
                v0.x += r0.x; v0.y += r0.y;
                v1.x += r1.x; v1.y += r1.y;
            }
            if (CVT) {
                v0.x = __uint_as_float(f2tf32(v0.x)); v0.y = __uint_as_float(f2tf32(v0.y));
                v1.x = __uint_as_float(f2tf32(v1.x)); v1.y = __uint_as_float(f2tf32(v1.y));
            }
            *(float2*)&C[i0] = v0;
            *(float2*)&C[i1] = v1;
        }
    }
}

// ---------------- Flash attention v3 ----------------
// q-tile 128, kv-tile 128 (NT=32), 256 threads (8 warps x 16 q-rows).
// K: reg-prefetch -> paired smem layout (LDS.64 B-frags, XOR swizzle, dblk stride 1028).
// V: cp.async double-buffered, direct layout [kv(perm)][d] stride 72.
// Q/K/V pre-rounded to tf32 by the projection GEMMs -> no cvt in staging.
#define TKV 128
#define NT (SKV / TKV)
#define ALDQ 140
#define KP_DBLK 1028            // 128 rows * 8 words + 4 pad
#define VLD 72
#define SM_Q (64 * ALDQ)        // 8960
#define SM_KP (8 * KP_DBLK)     // 8224
#define SM_V (TKV * VLD)        // 9216 per buffer
#define ATTN_SMEM_U32 (SM_Q + SM_KP + 2 * SM_V)

__global__ __launch_bounds__(256, 1) void attn_tf32(const float* __restrict__ mask) {
    extern __shared__ uint32_t sm[];
    uint32_t* Qs = sm;
    uint32_t* Kp = sm + SM_Q;
    uint32_t* Vb0 = Kp + SM_KP;
    uint32_t* Vb1 = Vb0 + SM_V;

    int b = blockIdx.z, h = blockIdx.y;
    int q0 = blockIdx.x * 128;
    int tid = threadIdx.x;
    int lane = tid & 31;
    int wid = tid >> 5;
    int g = lane >> 2, tig = lane & 3;
    int mbase = wid * 16;

    const float* mrow = mask + (size_t)b * SKV;

    // --- stage Q transposed: Qs[d][q] (pre-rounded tf32 bits) ---
    {
        int qrow = tid & 127, half = tid >> 7;
        const float* qp = g_q + (size_t)(b * SQ + q0 + qrow) * DM + h * DK + half * 32;
#pragma unroll
        for (int i = 0; i < 8; i++) {
            float4 v = *(const float4*)(qp + i * 4);
            int d0 = half * 32 + i * 4;
            Qs[(d0 + 0) * ALDQ + qrow] = __float_as_uint(v.x);
            Qs[(d0 + 1) * ALDQ + qrow] = __float_as_uint(v.y);
            Qs[(d0 + 2) * ALDQ + qrow] = __float_as_uint(v.z);
            Qs[(d0 + 3) * ALDQ + qrow] = __float_as_uint(v.w);
        }
    }
    __syncthreads();

    uint32_t qreg[8][4];
#pragma unroll
    for (int ks = 0; ks < 8; ks++) {
        int kb = ks * 8;
        qreg[ks][0] = Qs[(kb + tig) * ALDQ + mbase + g];
        qreg[ks][1] = Qs[(kb + tig) * ALDQ + mbase + g + 8];
        qreg[ks][2] = Qs[(kb + tig + 4) * ALDQ + mbase + g];
        qreg[ks][3] = Qs[(kb + tig + 4) * ALDQ + mbase + g + 8];
    }

    // --- staging thread mapping ---
    int dblk = tid & 7;            // K: 8 d per thread
    int rgrp = tid >> 3;           // K: 4 kv rows per thread
    int vr = tid & 127;            // V: 1 kv row
    int vh = (tid >> 7) * 32;      // V: 32 d per thread
    int vj = vr & 7;
    int vprow = (vr & ~7) | ((vj >> 1) + (vj & 1) * 4);
    const float* kbase = g_k + (size_t)(b * SKV) * DM + h * DK + dblk * 8;
    const float* vbase = g_v + (size_t)(b * SKV) * DM + h * DK + vh;

    uint32_t vdst0, vdst1;
    {
        uint32_t sbase = (uint32_t)__cvta_generic_to_shared(Vb0);
        vdst0 = sbase + (vprow * VLD + vh) * 4;
        vdst1 = vdst0 + SM_V * 4;
    }

    uint32_t kw[4][8];  // prefetched K rows (bits)

    // prefetch tile 0
#pragma unroll
    for (int i = 0; i < 4; i++) {
        const float* kp = kbase + (size_t)(rgrp * 4 + i) * DM;
        float4 a = *(const float4*)kp;
        float4 c = *(const float4*)(kp + 4);
        kw[i][0] = __float_as_uint(a.x); kw[i][1] = __float_as_uint(a.y);
        kw[i][2] = __float_as_uint(a.z); kw[i][3] = __float_as_uint(a.w);
        kw[i][4] = __float_as_uint(c.x); kw[i][5] = __float_as_uint(c.y);
        kw[i][6] = __float_as_uint(c.z); kw[i][7] = __float_as_uint(c.w);
    }
#pragma unroll
    for (int i = 0; i < 8; i++) {
        const float* vp = vbase + (size_t)vr * DM + i * 4;
        CP_ASYNC16(vdst0 + i * 16, vp);
    }
    CP_COMMIT();

    float m0s = -1e30f, m1s = -1e30f, l0 = 0.f, l1 = 0.f;
    float oacc[8][4];
#pragma unroll
    for (int d = 0; d < 8; d++)
#pragma unroll
        for (int e = 0; e < 4; e++) oacc[d][e] = 0.f;

    for (int jt = 0; jt < NT; jt++) {
        uint32_t* Vcur = (jt & 1) ? Vb1 : Vb0;
        __syncthreads();  // readers of Kp and V[other] done

        // store K regs -> paired layout (conflict-free STS.128, XOR swizzle per row)
#pragma unroll
        for (int i = 0; i < 4; i++) {
            int r = rgrp * 4 + i;
            int x = (r & 3) * 2;
            uint32_t* outp = Kp + dblk * KP_DBLK + r * 8;
            // val[inner] = kw[(inner&1)*4 + (inner>>1)]; stored word p = val[p^x]
            uint32_t val[8];
#pragma unroll
            for (int p = 0; p < 8; p++) {
                int inner = p ^ x;
                val[p] = kw[i][(inner & 1) * 4 + (inner >> 1)];
            }
            *(uint4*)(outp) = make_uint4(val[0], val[1], val[2], val[3]);
            *(uint4*)(outp + 4) = make_uint4(val[4], val[5], val[6], val[7]);
        }

        if (jt + 1 < NT) {
            // issue next V cp.async into other buffer
            uint32_t vdst = (jt & 1) ? vdst0 : vdst1;
            const float* vnext = vbase + (size_t)((jt + 1) * TKV + vr) * DM;
#pragma unroll
            for (int i = 0; i < 8; i++) CP_ASYNC16(vdst + i * 16, vnext + i * 4);
            CP_COMMIT();
            // prefetch next K into regs
#pragma unroll
            for (int i = 0; i < 4; i++) {
                const float* kp = kbase + (size_t)((jt + 1) * TKV + rgrp * 4 + i) * DM;
                float4 a = *(const float4*)kp;
                float4 c = *(const float4*)(kp + 4);
                kw[i][0] = __float_as_uint(a.x); kw[i][1] = __float_as_uint(a.y);
                kw[i][2] = __float_as_uint(a.z); kw[i][3] = __float_as_uint(a.w);
                kw[i][4] = __float_as_uint(c.x); kw[i][5] = __float_as_uint(c.y);
                kw[i][6] = __float_as_uint(c.z); kw[i][7] = __float_as_uint(c.w);
            }
            asm volatile("cp.async.wait_group 1;\n" ::: "memory");
        } else {
            asm volatile("cp.async.wait_group 0;\n" ::: "memory");
        }
        __syncthreads();  // K stores + V arrival visible

        // --- S = Q @ K^T over 128 kv ---
        float sacc[16][4];
#pragma unroll
        for (int n = 0; n < 16; n++)
#pragma unroll
            for (int e = 0; e < 4; e++) sacc[n][e] = 0.f;
#pragma unroll
        for (int ks = 0; ks < 8; ks++) {
            const uint32_t* kpd = Kp + ks * KP_DBLK;
#pragma unroll
            for (int n = 0; n < 16; n++) {
                int kv = n * 8 + g;
                int p0 = (tig * 2) ^ ((kv & 3) * 2);
                uint2 pair = *(const uint2*)(kpd + kv * 8 + p0);
                uint32_t bf[2] = {pair.x, pair.y};
                mma_tf32(sacc[n], qreg[ks], bf);
            }
        }

        // --- mask + online softmax ---
        float rmax0 = -1e30f, rmax1 = -1e30f;
#pragma unroll
        for (int n = 0; n < 16; n++) {
            float2 mk = *(const float2*)&mrow[jt * TKV + n * 8 + 2 * tig];
            sacc[n][0] += mk.x; sacc[n][1] += mk.y;
            sacc[n][2] += mk.x; sacc[n][3] += mk.y;
            rmax0 = fmaxf(rmax0, fmaxf(sacc[n][0], sacc[n][1]));
            rmax1 = fmaxf(rmax1, fmaxf(sacc[n][2], sacc[n][3]));
        }
        rmax0 = fmaxf(rmax0, __shfl_xor_sync(0xffffffffu, rmax0, 1));
        rmax0 = fmaxf(rmax0, __shfl_xor_sync(0xffffffffu, rmax0, 2));
        rmax1 = fmaxf(rmax1, __shfl_xor_sync(0xffffffffu, rmax1, 1));
        rmax1 = fmaxf(rmax1, __shfl_xor_sync(0xffffffffu, rmax1, 2));
        float mn0 = fmaxf(m0s, rmax0), mn1 = fmaxf(m1s, rmax1);
        float sc0 = fast_exp(m0s - mn0), sc1 = fast_exp(m1s - mn1);
        m0s = mn0; m1s = mn1;
#pragma unroll
        for (int d = 0; d < 8; d++) {
            oacc[d][0] *= sc0; oacc[d][1] *= sc0;
            oacc[d][2] *= sc1; oacc[d][3] *= sc1;
        }
        float rs0 = 0.f, rs1 = 0.f;
#pragma unroll
        for (int n = 0; n < 16; n++) {
            sacc[n][0] = fast_exp(sacc[n][0] - mn0);
            sacc[n][1] = fast_exp(sacc[n][1] - mn0);
            sacc[n][2] = fast_exp(sacc[n][2] - mn1);
            sacc[n][3] = fast_exp(sacc[n][3] - mn1);
            rs0 += sacc[n][0] + sacc[n][1];
            rs1 += sacc[n][2] + sacc[n][3];
        }
        rs0 += __shfl_xor_sync(0xffffffffu, rs0, 1);
        rs0 += __shfl_xor_sync(0xffffffffu, rs0, 2);
        rs1 += __shfl_xor_sync(0xffffffffu, rs1, 1);
        rs1 += __shfl_xor_sync(0xffffffffu, rs1, 2);
        l0 = l0 * sc0 + rs0;
        l1 = l1 * sc1 + rs1;

        // --- O += P @ V (P from registers; V rows pre-permuted) ---
#pragma unroll
        for (int ks = 0; ks < 16; ks++) {
            int kb = ks * 8;
            uint32_t pf[4];
            pf[0] = f2tf32(sacc[ks][0]);
            pf[1] = f2tf32(sacc[ks][2]);
            pf[2] = f2tf32(sacc[ks][1]);
            pf[3] = f2tf32(sacc[ks][3]);
            const uint32_t* v0p = Vcur + (kb + tig) * VLD + g;
            const uint32_t* v1p = Vcur + (kb + tig + 4) * VLD + g;
#pragma unroll
            for (int n = 0; n < 8; n++) {
                uint32_t vf[2] = {v0p[n * 8], v1p[n * 8]};
                mma_tf32(oacc[n], pf, vf);
            }
        }
    }

    float inv0 = 1.0f / l0, inv1 = 1.0f / l1;
    int row0 = q0 + mbase + g;
    float* cp0 = g_ctx + (size_t)(b * SQ + row0) * DM + h * DK;
    float* cp1 = g_ctx + (size_t)(b * SQ + row0 + 8) * DM + h * DK;
#pragma unroll
    for (int n = 0; n < 8; n++) {
        int col = n * 8 + 2 * tig;
        *(float2*)&cp0[col] = make_float2(oacc[n][0] * inv0, oacc[n][1] * inv0);
        *(float2*)&cp1[col] = make_float2(oacc[n][2] * inv1, oacc[n][3] * inv1);
    }
}

// ---------------- launch ----------------
extern "C" void kernel_launch(void* const* d_in, const int* in_sizes, int n_in,
                              void* d_out, int out_size) {
    const float* hidden = (const float*)d_in[0];
    const float* kv     = (const float*)d_in[1];
    const float* mask   = (const float*)d_in[2];
    const float* lnw    = (const float*)d_in[3];
    const float* Wq     = (const float*)d_in[4];
    const float* Wk     = (const float*)d_in[5];
    const float* Wv     = (const float*)d_in[6];
    const float* Wo     = (const float*)d_in[7];
    float* out = (float*)d_out;

    float *p_normed, *p_q, *p_k, *p_v, *p_ctx;
    cudaGetSymbolAddress((void**)&p_normed, g_normed);
    cudaGetSymbolAddress((void**)&p_q, g_q);
    cudaGetSymbolAddress((void**)&p_k, g_k);
    cudaGetSymbolAddress((void**)&p_v, g_v);
    cudaGetSymbolAddress((void**)&p_ctx, g_ctx);

    rmsnorm_kernel<<<BB * SQ, 256>>>(hidden, lnw);

    dim3 gq(DM / 128, (BB * SQ) / 128);
    dim3 gkv(DM / 128, (BB * SKV) / 128);
    tf32_gemm<false, true><<<gq, 128>>>(p_normed, Wq, nullptr, p_q, BB * SQ, DM, DM);
    tf32_gemm<false, true><<<gkv, 128>>>(kv, Wk, nullptr, p_k, BB * SKV, DM, DM);
    tf32_gemm<false, true><<<gkv, 128>>>(kv, Wv, nullptr, p_v, BB * SKV, DM, DM);

    const int ATTN_SMEM = ATTN_SMEM_U32 * 4;
    cudaFuncSetAttribute(attn_tf32, cudaFuncAttributeMaxDynamicSharedMemorySize, ATTN_SMEM);
    dim3 ga(SQ / 128, NH, BB);
    attn_tf32<<<ga, 256, ATTN_SMEM>>>(mask);

    tf32_gemm<true, false><<<gq, 128>>>(p_ctx, Wo, hidden, out, BB * SQ, DM, DM);
}